// round 9
// baseline (speedup 1.0000x reference)
#include <cuda_runtime.h>
#include <cuda_bf16.h>
#include <math_constants.h>
#include <cstdint>

// Problem constants
#define NN    8192
#define HID   128
#define HEADS 4
#define HD    32
#define OUTD  40
#define RSQRT_HD 0.17677669529663687f  // 1/sqrt(32)
#define L2E      1.4426950408889634f

// ---------------- scratch (device globals) ----------------
__device__ float          g_h  [NN * HID];   // h = x@W_in^T + b_in (fp32 residual)
__device__ __nv_bfloat16  g_qb [NN * HID];   // Q * rsqrt(hd), bf16 [token][h*32+d]
__device__ __nv_bfloat16  g_kb [NN * HID];   // K bf16 [token][h*32+d]
__device__ __nv_bfloat16  g_vt [HID * NN];   // V bf16 transposed [h*32+d][token]
__device__ float          g_ao [NN * HID];   // attention output
__device__ float          g_h2 [NN * HID];   // h + relu(out_proj)

// ---------------- small asm helpers ----------------
__device__ __forceinline__ uint32_t smem_u32(const void* p){
    uint32_t a;
    asm("{ .reg .u64 t; cvta.to.shared.u64 t, %1; cvt.u32.u64 %0, t; }" : "=r"(a) : "l"(p));
    return a;
}
__device__ __forceinline__ void ldsm4(uint32_t r[4], uint32_t addr){
    asm volatile("ldmatrix.sync.aligned.m8n8.x4.shared.b16 {%0,%1,%2,%3}, [%4];"
        : "=r"(r[0]), "=r"(r[1]), "=r"(r[2]), "=r"(r[3]) : "r"(addr));
}
__device__ __forceinline__ void mma16816(float c[4], const uint32_t a[4], const uint32_t b[2]){
    asm volatile("mma.sync.aligned.m16n8k16.row.col.f32.bf16.bf16.f32 "
        "{%0,%1,%2,%3}, {%4,%5,%6,%7}, {%8,%9}, {%0,%1,%2,%3};"
        : "+f"(c[0]), "+f"(c[1]), "+f"(c[2]), "+f"(c[3])
        : "r"(a[0]), "r"(a[1]), "r"(a[2]), "r"(a[3]), "r"(b[0]), "r"(b[1]));
}
__device__ __forceinline__ float ex2f(float x){
    float r; asm("ex2.approx.f32 %0, %1;" : "=f"(r) : "f"(x)); return r;
}
__device__ __forceinline__ uint32_t packbf(float hi, float lo){
    uint32_t r; asm("cvt.rn.bf16x2.f32 %0, %1, %2;" : "=r"(r) : "f"(hi), "f"(lo)); return r;
}

// bias2 = (scale * nan_to_num(1/nan_to_num(sp,-1), 0) - m) * log2(e)
__device__ __forceinline__ float bias2_of(float s, float scale, float nml2e){
    if (isnan(s) || isinf(s)) s = -1.0f;
    float r = __fdividef(1.0f, s);            // 1/0 -> +inf
    if (isnan(r) || isinf(r)) r = 0.0f;
    return fmaf(scale * r, L2E, nml2e);       // (scale*r - m)*L2E
}

// ---------------- GEMM: C[M,CO] = A[M,128] @ W[CO,128]^T + b ----------------
// mode 0: plain fp32 ; mode 1: C = R + relu(.) ; mode 2: qkv -> bf16 Q/K/Vt
#define GEMM_SMEM_FLOATS (2*128*64 + 64*132)
#define GEMM_SMEM_BYTES  (GEMM_SMEM_FLOATS * 4)

__global__ __launch_bounds__(256, 2)
void gemm_k(const float* __restrict__ A, const float* __restrict__ W,
            const float* __restrict__ bias, const float* __restrict__ R,
            float* __restrict__ C, int CO, int mode,
            __nv_bfloat16* __restrict__ qb, __nv_bfloat16* __restrict__ kb,
            __nv_bfloat16* __restrict__ vt)
{
    extern __shared__ float sm[];
    float* At  = sm;
    float* Wt  = sm + 128*64;
    float* Stg = sm + 2*128*64;

    const int r0  = blockIdx.x * 64;
    const int c0  = blockIdx.y * 64;
    const int tid = threadIdx.x;

    {   // stage A
        const float4* Af4 = (const float4*)(A + (size_t)r0 * 128);
        float4* Sf4 = (float4*)Stg;
        #pragma unroll
        for (int i = 0; i < 8; i++) {
            int idx = tid + 256*i;
            int r = idx >> 5, d4 = idx & 31;
            Sf4[r*33 + d4] = Af4[r*32 + d4];
        }
    }
    __syncthreads();
    {   // transpose A
        #pragma unroll
        for (int i = 0; i < 8; i++) {
            int idx = tid + 256*i;
            int r = idx & 63, d4 = idx >> 6;
            float4 v = *(const float4*)&Stg[r*132 + d4*4];
            At[(4*d4+0)*64 + r] = v.x; At[(4*d4+1)*64 + r] = v.y;
            At[(4*d4+2)*64 + r] = v.z; At[(4*d4+3)*64 + r] = v.w;
        }
    }
    __syncthreads();
    {   // stage W
        const float4* Wf4 = (const float4*)W;
        float4* Sf4 = (float4*)Stg;
        #pragma unroll
        for (int i = 0; i < 8; i++) {
            int idx = tid + 256*i;
            int c = idx >> 5, d4 = idx & 31;
            float4 v = make_float4(0.f,0.f,0.f,0.f);
            if (c0 + c < CO) v = Wf4[(size_t)(c0 + c)*32 + d4];
            Sf4[c*33 + d4] = v;
        }
    }
    __syncthreads();
    {   // transpose W
        #pragma unroll
        for (int i = 0; i < 8; i++) {
            int idx = tid + 256*i;
            int c = idx & 63, d4 = idx >> 6;
            float4 v = *(const float4*)&Stg[c*132 + d4*4];
            Wt[(4*d4+0)*64 + c] = v.x; Wt[(4*d4+1)*64 + c] = v.y;
            Wt[(4*d4+2)*64 + c] = v.z; Wt[(4*d4+3)*64 + c] = v.w;
        }
    }
    __syncthreads();

    const int tr = tid >> 4;
    const int tc = tid & 15;
    float acc[4][4];
    #pragma unroll
    for (int i = 0; i < 4; i++)
        #pragma unroll
        for (int j = 0; j < 4; j++) acc[i][j] = 0.f;

    #pragma unroll 8
    for (int d = 0; d < 128; d++) {
        float4 a = *(const float4*)&At[d*64 + tr*4];
        float4 w = *(const float4*)&Wt[d*64 + tc*4];
        float av[4] = {a.x, a.y, a.z, a.w};
        float wv[4] = {w.x, w.y, w.z, w.w};
        #pragma unroll
        for (int i = 0; i < 4; i++)
            #pragma unroll
            for (int j = 0; j < 4; j++)
                acc[i][j] = fmaf(av[i], wv[j], acc[i][j]);
    }

    #pragma unroll
    for (int i = 0; i < 4; i++) {
        int r = r0 + tr*4 + i;
        #pragma unroll
        for (int j = 0; j < 4; j++) {
            int c = c0 + tc*4 + j;
            if (c < CO) {
                float v = acc[i][j] + bias[c];
                if (mode == 2) {
                    if (c < 128)      qb[(size_t)r*128 + c]       = __float2bfloat16(v * RSQRT_HD);
                    else if (c < 256) kb[(size_t)r*128 + (c-128)] = __float2bfloat16(v);
                    else              vt[(size_t)(c-256)*NN + r]  = __float2bfloat16(v);
                } else {
                    if (mode == 1) v = R[(size_t)r*128 + c] + fmaxf(v, 0.f);
                    C[(size_t)r*CO + c] = v;
                }
            }
        }
    }
}

// ---------------- tensor-core flash attention ----------------
// CTA: 32 queries x ALL 4 heads x all 8192 keys (64-key blocks).
// 8 warps: warp w -> head w>>1, query m16-tile (w&1)*16.
// Smem (single-buffered):
//   Ks: [64 keys][16 chunks of 16B]  stride 272B   (also used to stage Q)
//   Vs: [128 rows = h*32+d][64 keys] stride 144B
//   Bs: [32 q][64 k] fp32 bias2      stride 288B
#define KS_OFF   0
#define VS_OFF   17408
#define BS_OFF   35840
#define ATTN_SMEM 45056

__global__ __launch_bounds__(256, 2)
void attn_k(const __nv_bfloat16* __restrict__ qb_g, const __nv_bfloat16* __restrict__ kb_g,
            const __nv_bfloat16* __restrict__ vt_g, const float* __restrict__ sp,
            const float* __restrict__ scale_ptr, float* __restrict__ out)
{
    extern __shared__ char smc[];
    const uint32_t sb = smem_u32(smc);
    const int tid  = threadIdx.x;
    const int lane = tid & 31;
    const int wid  = tid >> 5;
    const int h    = wid >> 1;
    const int qbo  = (wid & 1) * 16;
    const int q0   = blockIdx.x * 32;

    const float scale = scale_ptr[0];
    const float nml2e = -(scale + 8.0f) * L2E;    // -(m)*log2e, m = scale+8

    // ---- stage Q (32 rows x 256B) into Ks region, build A fragments ----
    {
        const uint4* qsrc = (const uint4*)(qb_g + (size_t)q0 * 128);
        #pragma unroll
        for (int i = 0; i < 2; i++) {
            int idx = tid + 256*i;
            int r = idx >> 4, c = idx & 15;
            *(uint4*)(smc + KS_OFF + r*272 + c*16) = qsrc[r*16 + c];
        }
    }
    __syncthreads();
    uint32_t qa[2][4];
    {
        uint32_t qaddr = sb + KS_OFF + (qbo + (lane & 15))*272 + (h*4 + (lane >> 4))*16;
        ldsm4(qa[0], qaddr);
        ldsm4(qa[1], qaddr + 32);
    }
    __syncthreads();

    // loop-invariant per-lane ldsm/lds addresses
    const uint32_t kaddr = sb + KS_OFF + ((lane & 7) + ((lane >> 4) & 1)*8)*272
                           + h*64 + ((lane >> 3) & 1)*16;
    const uint32_t vaddr = sb + VS_OFF + (h*32 + (lane & 7) + ((lane >> 4) & 1)*8)*144
                           + ((lane >> 3) & 1)*16;
    const uint32_t baddr = sb + BS_OFF + (qbo + (lane >> 2))*288 + (lane & 3)*8;

    float O[4][4];
    #pragma unroll
    for (int i = 0; i < 4; i++)
        #pragma unroll
        for (int j = 0; j < 4; j++) O[i][j] = 0.f;
    float l0 = 0.f, l1 = 0.f;

    const uint4* ksrc = (const uint4*)kb_g;   // row = 16 uint4
    const uint4* vsrc = (const uint4*)vt_g;   // row = 1024 uint4

    for (int kb = 0; kb < NN/64; kb++) {
        const int k0 = kb * 64;
        // ---- load K tile ----
        #pragma unroll
        for (int i = 0; i < 4; i++) {
            int idx = tid + 256*i;
            int r = idx >> 4, c = idx & 15;
            *(uint4*)(smc + KS_OFF + r*272 + c*16) = ksrc[(size_t)(k0 + r)*16 + c];
        }
        // ---- load V^T tile ----
        #pragma unroll
        for (int i = 0; i < 4; i++) {
            int idx = tid + 256*i;
            int r = idx >> 3, c = idx & 7;
            *(uint4*)(smc + VS_OFF + r*144 + c*16) = vsrc[(size_t)r*1024 + (k0 >> 3) + c];
        }
        // ---- load + transform bias tile ----
        #pragma unroll
        for (int i = 0; i < 2; i++) {
            int idx = tid + 256*i;
            int qq = idx >> 4, c4 = idx & 15;
            float4 s4 = *(const float4*)(sp + (size_t)(q0 + qq)*NN + k0 + c4*4);
            float4 b4;
            b4.x = bias2_of(s4.x, scale, nml2e);
            b4.y = bias2_of(s4.y, scale, nml2e);
            b4.z = bias2_of(s4.z, scale, nml2e);
            b4.w = bias2_of(s4.w, scale, nml2e);
            *(float4*)(smc + BS_OFF + qq*288 + c4*16) = b4;
        }
        __syncthreads();

        // ---- S = Q K^T  (1 m-tile x 8 n-tiles x 2 k-steps) ----
        float S[8][4];
        #pragma unroll
        for (int j = 0; j < 8; j++)
            #pragma unroll
            for (int t = 0; t < 4; t++) S[j][t] = 0.f;
        #pragma unroll
        for (int s = 0; s < 2; s++) {
            #pragma unroll
            for (int p = 0; p < 4; p++) {      // n-tile pairs
                uint32_t kbf[4];
                ldsm4(kbf, kaddr + p*(16*272) + s*32);
                mma16816(S[2*p],   qa[s], kbf);
                mma16816(S[2*p+1], qa[s], kbf + 2);
            }
        }

        // ---- softmax (fixed shift), pack P to bf16 A-fragments ----
        uint32_t pk[4][4];
        #pragma unroll
        for (int j = 0; j < 8; j++) {
            float b0, b1, b2, b3;
            asm volatile("ld.shared.v2.f32 {%0,%1}, [%2];"
                         : "=f"(b0), "=f"(b1) : "r"(baddr + j*32));
            asm volatile("ld.shared.v2.f32 {%0,%1}, [%2];"
                         : "=f"(b2), "=f"(b3) : "r"(baddr + j*32 + 8*288));
            float p0 = ex2f(fmaf(S[j][0], L2E, b0));
            float p1 = ex2f(fmaf(S[j][1], L2E, b1));
            float p2 = ex2f(fmaf(S[j][2], L2E, b2));
            float p3 = ex2f(fmaf(S[j][3], L2E, b3));
            l0 += p0 + p1;
            l1 += p2 + p3;
            int s = j >> 1, o = (j & 1) * 2;
            pk[s][o]     = packbf(p1, p0);
            pk[s][o + 1] = packbf(p3, p2);
        }

        // ---- O += P V  (4 k-steps x 4 d-tiles) ----
        #pragma unroll
        for (int s = 0; s < 4; s++) {
            uint32_t vb[8];
            ldsm4(vb,     vaddr + s*32);              // d-tiles 0,1
            ldsm4(vb + 4, vaddr + 16*144 + s*32);     // d-tiles 2,3
            mma16816(O[0], pk[s], vb);
            mma16816(O[1], pk[s], vb + 2);
            mma16816(O[2], pk[s], vb + 4);
            mma16816(O[3], pk[s], vb + 6);
        }
        __syncthreads();
    }

    // ---- finalize: row sums across quads, normalize, store ----
    l0 += __shfl_xor_sync(0xffffffffu, l0, 1);
    l0 += __shfl_xor_sync(0xffffffffu, l0, 2);
    l1 += __shfl_xor_sync(0xffffffffu, l1, 1);
    l1 += __shfl_xor_sync(0xffffffffu, l1, 2);
    const float i0 = 1.0f / l0;
    const float i1 = 1.0f / l1;

    const int r  = q0 + qbo + (lane >> 2);
    const int cb = h*32 + 2*(lane & 3);
    #pragma unroll
    for (int j = 0; j < 4; j++) {
        float2 v0 = make_float2(O[j][0]*i0, O[j][1]*i0);
        float2 v1 = make_float2(O[j][2]*i1, O[j][3]*i1);
        *(float2*)(out + (size_t)r*128 + cb + 8*j)       = v0;
        *(float2*)(out + (size_t)(r+8)*128 + cb + 8*j)   = v1;
    }
}

// ---------------- log_softmax over last dim (40), in-place ----------------
__global__ __launch_bounds__(256)
void logsoftmax_k(float* __restrict__ io)
{
    int row  = blockIdx.x * 8 + (threadIdx.x >> 5);
    int lane = threadIdx.x & 31;
    float* p = io + (size_t)row * OUTD;

    float a = p[lane];
    float b = (lane < 8) ? p[lane + 32] : -CUDART_INF_F;

    float mx = fmaxf(a, b);
    #pragma unroll
    for (int off = 16; off; off >>= 1)
        mx = fmaxf(mx, __shfl_xor_sync(0xffffffffu, mx, off));

    float e = __expf(a - mx) + ((lane < 8) ? __expf(b - mx) : 0.f);
    #pragma unroll
    for (int off = 16; off; off >>= 1)
        e += __shfl_xor_sync(0xffffffffu, e, off);

    float lse = mx + logf(e);
    p[lane] = a - lse;
    if (lane < 8) p[lane + 32] = b - lse;
}

// ---------------- launch ----------------
extern "C" void kernel_launch(void* const* d_in, const int* in_sizes, int n_in,
                              void* d_out, int out_size)
{
    (void)in_sizes; (void)n_in; (void)out_size;
    const float* x     = (const float*)d_in[0];
    // d_in[1] = pos_enc, unused in forward (faithful to reference)
    const float* sp    = (const float*)d_in[2];
    const float* W_in  = (const float*)d_in[3];
    const float* b_in  = (const float*)d_in[4];
    const float* ipw   = (const float*)d_in[5];
    const float* ipb   = (const float*)d_in[6];
    const float* opw   = (const float*)d_in[7];
    const float* opb   = (const float*)d_in[8];
    const float* Wout  = (const float*)d_in[9];
    const float* bout  = (const float*)d_in[10];
    const float* scale = (const float*)d_in[11];
    float* out = (float*)d_out;

    float *gh, *gao, *gh2;
    __nv_bfloat16 *gqb, *gkb, *gvt;
    cudaGetSymbolAddress((void**)&gh,  g_h);
    cudaGetSymbolAddress((void**)&gao, g_ao);
    cudaGetSymbolAddress((void**)&gh2, g_h2);
    cudaGetSymbolAddress((void**)&gqb, g_qb);
    cudaGetSymbolAddress((void**)&gkb, g_kb);
    cudaGetSymbolAddress((void**)&gvt, g_vt);

    cudaFuncSetAttribute(gemm_k, cudaFuncAttributeMaxDynamicSharedMemorySize, GEMM_SMEM_BYTES);
    cudaFuncSetAttribute(attn_k, cudaFuncAttributeMaxDynamicSharedMemorySize, ATTN_SMEM);

    // h = x @ W_in^T + b_in
    gemm_k<<<dim3(NN/64, 2), 256, GEMM_SMEM_BYTES>>>(x, W_in, b_in, nullptr, gh, HID, 0,
                                                     nullptr, nullptr, nullptr);
    // qkv = h @ in_proj_w^T + b  -> bf16 Q (pre-scaled), K, V^T
    gemm_k<<<dim3(NN/64, 6), 256, GEMM_SMEM_BYTES>>>(gh, ipw, ipb, nullptr, nullptr, 3*HID, 2,
                                                     gqb, gkb, gvt);
    // tensor-core flash attention
    attn_k<<<NN/32, 256, ATTN_SMEM>>>(gqb, gkb, gvt, sp, scale, gao);
    // h2 = h + relu(ao @ out_proj^T + b)
    gemm_k<<<dim3(NN/64, 2), 256, GEMM_SMEM_BYTES>>>(gao, opw, opb, gh, gh2, HID, 1,
                                                     nullptr, nullptr, nullptr);
    // logits = h2 @ W_out^T + b_out
    gemm_k<<<dim3(NN/64, 1), 256, GEMM_SMEM_BYTES>>>(gh2, Wout, bout, nullptr, out, OUTD, 0,
                                                     nullptr, nullptr, nullptr);
    // log_softmax in-place
    logsoftmax_k<<<NN/8, 256>>>(out);
}

// round 10
// speedup vs baseline: 1.1059x; 1.1059x over previous
#include <cuda_runtime.h>
#include <cuda_bf16.h>
#include <math_constants.h>
#include <cstdint>

#define NN    8192
#define HID   128
#define OUTD  40
#define RSQRT_HD 0.17677669529663687f
#define L2E      1.4426950408889634f

__device__ float          g_h  [NN * HID];
__device__ __nv_bfloat16  g_qb [NN * HID];
__device__ __nv_bfloat16  g_kb [NN * HID];
__device__ __nv_bfloat16  g_vt [HID * NN];
__device__ float          g_ao [NN * HID];
__device__ float          g_h2 [NN * HID];

__device__ __forceinline__ uint32_t smem_u32(const void* p){
    uint32_t a;
    asm("{ .reg .u64 t; cvta.to.shared.u64 t, %1; cvt.u32.u64 %0, t; }" : "=r"(a) : "l"(p));
    return a;
}
__device__ __forceinline__ void ldsm4(uint32_t r[4], uint32_t addr){
    asm volatile("ldmatrix.sync.aligned.m8n8.x4.shared.b16 {%0,%1,%2,%3}, [%4];"
        : "=r"(r[0]), "=r"(r[1]), "=r"(r[2]), "=r"(r[3]) : "r"(addr));
}
__device__ __forceinline__ void mma16816(float c[4], const uint32_t a[4], const uint32_t b[2]){
    asm volatile("mma.sync.aligned.m16n8k16.row.col.f32.bf16.bf16.f32 "
        "{%0,%1,%2,%3}, {%4,%5,%6,%7}, {%8,%9}, {%0,%1,%2,%3};"
        : "+f"(c[0]), "+f"(c[1]), "+f"(c[2]), "+f"(c[3])
        : "r"(a[0]), "r"(a[1]), "r"(a[2]), "r"(a[3]), "r"(b[0]), "r"(b[1]));
}
__device__ __forceinline__ float ex2f(float x){
    float r; asm("ex2.approx.f32 %0, %1;" : "=f"(r) : "f"(x)); return r;
}
__device__ __forceinline__ uint32_t packbf(float hi, float lo){
    uint32_t r; asm("cvt.rn.bf16x2.f32 %0, %1, %2;" : "=r"(r) : "f"(hi), "f"(lo)); return r;
}
__device__ __forceinline__ float bias2_of(float s, float scale, float nml2e){
    if (isnan(s) || isinf(s)) s = -1.0f;
    float r = __fdividef(1.0f, s);
    if (isnan(r) || isinf(r)) r = 0.0f;
    return fmaf(scale * r, L2E, nml2e);
}

// ---------------- GEMM (unchanged from R6) ----------------
#define GEMM_SMEM_FLOATS (2*128*64 + 64*132)
#define GEMM_SMEM_BYTES  (GEMM_SMEM_FLOATS * 4)

__global__ __launch_bounds__(256, 2)
void gemm_k(const float* __restrict__ A, const float* __restrict__ W,
            const float* __restrict__ bias, const float* __restrict__ R,
            float* __restrict__ C, int CO, int mode,
            __nv_bfloat16* __restrict__ qb, __nv_bfloat16* __restrict__ kb,
            __nv_bfloat16* __restrict__ vt)
{
    extern __shared__ float sm[];
    float* At  = sm;
    float* Wt  = sm + 128*64;
    float* Stg = sm + 2*128*64;
    const int r0  = blockIdx.x * 64;
    const int c0  = blockIdx.y * 64;
    const int tid = threadIdx.x;

    {
        const float4* Af4 = (const float4*)(A + (size_t)r0 * 128);
        float4* Sf4 = (float4*)Stg;
        #pragma unroll
        for (int i = 0; i < 8; i++) {
            int idx = tid + 256*i;
            int r = idx >> 5, d4 = idx & 31;
            Sf4[r*33 + d4] = Af4[r*32 + d4];
        }
    }
    __syncthreads();
    {
        #pragma unroll
        for (int i = 0; i < 8; i++) {
            int idx = tid + 256*i;
            int r = idx & 63, d4 = idx >> 6;
            float4 v = *(const float4*)&Stg[r*132 + d4*4];
            At[(4*d4+0)*64 + r] = v.x; At[(4*d4+1)*64 + r] = v.y;
            At[(4*d4+2)*64 + r] = v.z; At[(4*d4+3)*64 + r] = v.w;
        }
    }
    __syncthreads();
    {
        const float4* Wf4 = (const float4*)W;
        float4* Sf4 = (float4*)Stg;
        #pragma unroll
        for (int i = 0; i < 8; i++) {
            int idx = tid + 256*i;
            int c = idx >> 5, d4 = idx & 31;
            float4 v = make_float4(0.f,0.f,0.f,0.f);
            if (c0 + c < CO) v = Wf4[(size_t)(c0 + c)*32 + d4];
            Sf4[c*33 + d4] = v;
        }
    }
    __syncthreads();
    {
        #pragma unroll
        for (int i = 0; i < 8; i++) {
            int idx = tid + 256*i;
            int c = idx & 63, d4 = idx >> 6;
            float4 v = *(const float4*)&Stg[c*132 + d4*4];
            Wt[(4*d4+0)*64 + c] = v.x; Wt[(4*d4+1)*64 + c] = v.y;
            Wt[(4*d4+2)*64 + c] = v.z; Wt[(4*d4+3)*64 + c] = v.w;
        }
    }
    __syncthreads();

    const int tr = tid >> 4;
    const int tc = tid & 15;
    float acc[4][4];
    #pragma unroll
    for (int i = 0; i < 4; i++)
        #pragma unroll
        for (int j = 0; j < 4; j++) acc[i][j] = 0.f;

    #pragma unroll 8
    for (int d = 0; d < 128; d++) {
        float4 a = *(const float4*)&At[d*64 + tr*4];
        float4 w = *(const float4*)&Wt[d*64 + tc*4];
        float av[4] = {a.x, a.y, a.z, a.w};
        float wv[4] = {w.x, w.y, w.z, w.w};
        #pragma unroll
        for (int i = 0; i < 4; i++)
            #pragma unroll
            for (int j = 0; j < 4; j++)
                acc[i][j] = fmaf(av[i], wv[j], acc[i][j]);
    }

    #pragma unroll
    for (int i = 0; i < 4; i++) {
        int r = r0 + tr*4 + i;
        #pragma unroll
        for (int j = 0; j < 4; j++) {
            int c = c0 + tc*4 + j;
            if (c < CO) {
                float v = acc[i][j] + bias[c];
                if (mode == 2) {
                    if (c < 128)      qb[(size_t)r*128 + c]       = __float2bfloat16(v * RSQRT_HD);
                    else if (c < 256) kb[(size_t)r*128 + (c-128)] = __float2bfloat16(v);
                    else              vt[(size_t)(c-256)*NN + r]  = __float2bfloat16(v);
                } else {
                    if (mode == 1) v = R[(size_t)r*128 + c] + fmaxf(v, 0.f);
                    C[(size_t)r*CO + c] = v;
                }
            }
        }
    }
}

// ---------------- flash attention: 64 queries x 4 heads per CTA ----------------
// 8 warps: warp w -> head w>>1, query-half (w&1)*32 (two m16 tiles each).
// Smem: Ks [64k][272B], Vs [128d][144B], Bs [64q][288B fp32 bias2].
// Register-prefetched single-buffer pipeline: LDG(next) overlaps compute(cur).
#define KS_OFF   0
#define VS_OFF   17408
#define BS_OFF   35840
#define ATTN_SMEM 54272

__global__ __launch_bounds__(256, 1)
void attn_k(const __nv_bfloat16* __restrict__ qb_g, const __nv_bfloat16* __restrict__ kb_g,
            const __nv_bfloat16* __restrict__ vt_g, const float* __restrict__ sp,
            const float* __restrict__ scale_ptr, float* __restrict__ out)
{
    extern __shared__ char smc[];
    const uint32_t sb = smem_u32(smc);
    const int tid  = threadIdx.x;
    const int lane = tid & 31;
    const int wid  = tid >> 5;
    const int h    = wid >> 1;
    const int qh   = wid & 1;            // query half
    const int q0   = blockIdx.x * 64;

    const float scale = scale_ptr[0];
    const float nml2e = -(scale + 8.0f) * L2E;

    // ---- stage Q (64 rows x 256B) into Ks region, build A fragments ----
    {
        const uint4* qsrc = (const uint4*)(qb_g + (size_t)q0 * 128);
        #pragma unroll
        for (int i = 0; i < 4; i++) {
            int idx = tid + 256*i;
            int r = idx >> 4, c = idx & 15;
            *(uint4*)(smc + KS_OFF + r*272 + c*16) = qsrc[r*16 + c];
        }
    }
    __syncthreads();
    uint32_t qa[2][2][4];
    #pragma unroll
    for (int mt = 0; mt < 2; mt++) {
        uint32_t qaddr = sb + KS_OFF + (qh*32 + mt*16 + (lane & 15))*272
                         + (h*4 + (lane >> 4))*16;
        ldsm4(qa[mt][0], qaddr);
        ldsm4(qa[mt][1], qaddr + 32);
    }
    // first loop sync protects Q reads before K overwrite

    const uint32_t kaddr = sb + KS_OFF + ((lane & 7) + ((lane >> 4) & 1)*8)*272
                           + h*64 + ((lane >> 3) & 1)*16;
    const uint32_t vaddr = sb + VS_OFF + (h*32 + (lane & 7) + ((lane >> 4) & 1)*8)*144
                           + ((lane >> 3) & 1)*16;
    const uint32_t baddr = sb + BS_OFF + (qh*32 + (lane >> 2))*288 + (lane & 3)*8;

    float O[2][4][4];
    #pragma unroll
    for (int mt = 0; mt < 2; mt++)
        #pragma unroll
        for (int i = 0; i < 4; i++)
            #pragma unroll
            for (int j = 0; j < 4; j++) O[mt][i][j] = 0.f;
    float lsum[2][2] = {{0.f,0.f},{0.f,0.f}};

    const uint4* ksrc = (const uint4*)kb_g;   // row = 16 uint4
    const uint4* vsrc = (const uint4*)vt_g;   // row = 1024 uint4

    // per-thread load indices
    const int kr = tid >> 4,  kc = tid & 15;  // K/bias pattern (i-stride 16 rows)
    const int vr = tid >> 3,  vc = tid & 7;   // V pattern (i-stride 32 rows)

    uint4  krg[4], vrg[4];
    float4 brg[4];
    // preload iter 0
    #pragma unroll
    for (int i = 0; i < 4; i++) {
        krg[i] = ksrc[(size_t)(kr + 16*i)*16 + kc];
        vrg[i] = vsrc[(size_t)(vr + 32*i)*1024 + vc];
        brg[i] = *(const float4*)(sp + (size_t)(q0 + kr + 16*i)*NN + kc*4);
    }

    for (int kb = 0; kb < NN/64; kb++) {
        __syncthreads();   // smem free (prev compute / Q reads done)
        #pragma unroll
        for (int i = 0; i < 4; i++) {
            *(uint4*)(smc + KS_OFF + (kr + 16*i)*272 + kc*16) = krg[i];
            *(uint4*)(smc + VS_OFF + (vr + 32*i)*144 + vc*16) = vrg[i];
            float4 s4 = brg[i], b4;
            b4.x = bias2_of(s4.x, scale, nml2e);
            b4.y = bias2_of(s4.y, scale, nml2e);
            b4.z = bias2_of(s4.z, scale, nml2e);
            b4.w = bias2_of(s4.w, scale, nml2e);
            *(float4*)(smc + BS_OFF + (kr + 16*i)*288 + kc*16) = b4;
        }
        __syncthreads();   // tiles ready

        if (kb + 1 < NN/64) {   // prefetch next (overlaps compute)
            const int k0n = (kb + 1) * 64;
            #pragma unroll
            for (int i = 0; i < 4; i++) {
                krg[i] = ksrc[(size_t)(k0n + kr + 16*i)*16 + kc];
                vrg[i] = vsrc[(size_t)(vr + 32*i)*1024 + (k0n >> 3) + vc];
                brg[i] = *(const float4*)(sp + (size_t)(q0 + kr + 16*i)*NN + k0n + kc*4);
            }
        }

        // ---- S = Q K^T : K fragments loaded once, used by both m-tiles ----
        float S[2][8][4];
        #pragma unroll
        for (int mt = 0; mt < 2; mt++)
            #pragma unroll
            for (int j = 0; j < 8; j++)
                #pragma unroll
                for (int t = 0; t < 4; t++) S[mt][j][t] = 0.f;
        #pragma unroll
        for (int s = 0; s < 2; s++) {
            #pragma unroll
            for (int p = 0; p < 4; p++) {
                uint32_t kbf[4];
                ldsm4(kbf, kaddr + p*(16*272) + s*32);
                #pragma unroll
                for (int mt = 0; mt < 2; mt++) {
                    mma16816(S[mt][2*p],   qa[mt][s], kbf);
                    mma16816(S[mt][2*p+1], qa[mt][s], kbf + 2);
                }
            }
        }

        // ---- softmax (fixed shift), pack P ----
        uint32_t pk[2][4][4];
        #pragma unroll
        for (int mt = 0; mt < 2; mt++) {
            const uint32_t bmt = baddr + mt*(16*288);
            #pragma unroll
            for (int j = 0; j < 8; j++) {
                float b0, b1, b2, b3;
                asm volatile("ld.shared.v2.f32 {%0,%1}, [%2];"
                             : "=f"(b0), "=f"(b1) : "r"(bmt + j*32));
                asm volatile("ld.shared.v2.f32 {%0,%1}, [%2];"
                             : "=f"(b2), "=f"(b3) : "r"(bmt + j*32 + 8*288));
                float p0 = ex2f(fmaf(S[mt][j][0], L2E, b0));
                float p1 = ex2f(fmaf(S[mt][j][1], L2E, b1));
                float p2 = ex2f(fmaf(S[mt][j][2], L2E, b2));
                float p3 = ex2f(fmaf(S[mt][j][3], L2E, b3));
                lsum[mt][0] += p0 + p1;
                lsum[mt][1] += p2 + p3;
                int s = j >> 1, o = (j & 1) * 2;
                pk[mt][s][o]     = packbf(p1, p0);
                pk[mt][s][o + 1] = packbf(p3, p2);
            }
        }

        // ---- O += P V : V fragments loaded once, used by both m-tiles ----
        #pragma unroll
        for (int s = 0; s < 4; s++) {
            uint32_t vb[8];
            ldsm4(vb,     vaddr + s*32);
            ldsm4(vb + 4, vaddr + 16*144 + s*32);
            #pragma unroll
            for (int mt = 0; mt < 2; mt++) {
                mma16816(O[mt][0], pk[mt][s], vb);
                mma16816(O[mt][1], pk[mt][s], vb + 2);
                mma16816(O[mt][2], pk[mt][s], vb + 4);
                mma16816(O[mt][3], pk[mt][s], vb + 6);
            }
        }
    }

    // ---- finalize ----
    #pragma unroll
    for (int mt = 0; mt < 2; mt++) {
        float l0 = lsum[mt][0], l1 = lsum[mt][1];
        l0 += __shfl_xor_sync(0xffffffffu, l0, 1);
        l0 += __shfl_xor_sync(0xffffffffu, l0, 2);
        l1 += __shfl_xor_sync(0xffffffffu, l1, 1);
        l1 += __shfl_xor_sync(0xffffffffu, l1, 2);
        const float i0 = 1.0f / l0;
        const float i1 = 1.0f / l1;
        const int r  = q0 + qh*32 + mt*16 + (lane >> 2);
        const int cb = h*32 + 2*(lane & 3);
        #pragma unroll
        for (int j = 0; j < 4; j++) {
            float2 v0 = make_float2(O[mt][j][0]*i0, O[mt][j][1]*i0);
            float2 v1 = make_float2(O[mt][j][2]*i1, O[mt][j][3]*i1);
            *(float2*)(out + (size_t)r*128 + cb + 8*j)     = v0;
            *(float2*)(out + (size_t)(r+8)*128 + cb + 8*j) = v1;
        }
    }
}

// ---------------- log_softmax (unchanged) ----------------
__global__ __launch_bounds__(256)
void logsoftmax_k(float* __restrict__ io)
{
    int row  = blockIdx.x * 8 + (threadIdx.x >> 5);
    int lane = threadIdx.x & 31;
    float* p = io + (size_t)row * OUTD;

    float a = p[lane];
    float b = (lane < 8) ? p[lane + 32] : -CUDART_INF_F;

    float mx = fmaxf(a, b);
    #pragma unroll
    for (int off = 16; off; off >>= 1)
        mx = fmaxf(mx, __shfl_xor_sync(0xffffffffu, mx, off));

    float e = __expf(a - mx) + ((lane < 8) ? __expf(b - mx) : 0.f);
    #pragma unroll
    for (int off = 16; off; off >>= 1)
        e += __shfl_xor_sync(0xffffffffu, e, off);

    float lse = mx + logf(e);
    p[lane] = a - lse;
    if (lane < 8) p[lane + 32] = b - lse;
}

// ---------------- launch ----------------
extern "C" void kernel_launch(void* const* d_in, const int* in_sizes, int n_in,
                              void* d_out, int out_size)
{
    (void)in_sizes; (void)n_in; (void)out_size;
    const float* x     = (const float*)d_in[0];
    const float* sp    = (const float*)d_in[2];
    const float* W_in  = (const float*)d_in[3];
    const float* b_in  = (const float*)d_in[4];
    const float* ipw   = (const float*)d_in[5];
    const float* ipb   = (const float*)d_in[6];
    const float* opw   = (const float*)d_in[7];
    const float* opb   = (const float*)d_in[8];
    const float* Wout  = (const float*)d_in[9];
    const float* bout  = (const float*)d_in[10];
    const float* scale = (const float*)d_in[11];
    float* out = (float*)d_out;

    float *gh, *gao, *gh2;
    __nv_bfloat16 *gqb, *gkb, *gvt;
    cudaGetSymbolAddress((void**)&gh,  g_h);
    cudaGetSymbolAddress((void**)&gao, g_ao);
    cudaGetSymbolAddress((void**)&gh2, g_h2);
    cudaGetSymbolAddress((void**)&gqb, g_qb);
    cudaGetSymbolAddress((void**)&gkb, g_kb);
    cudaGetSymbolAddress((void**)&gvt, g_vt);

    cudaFuncSetAttribute(gemm_k, cudaFuncAttributeMaxDynamicSharedMemorySize, GEMM_SMEM_BYTES);
    cudaFuncSetAttribute(attn_k, cudaFuncAttributeMaxDynamicSharedMemorySize, ATTN_SMEM);

    gemm_k<<<dim3(NN/64, 2), 256, GEMM_SMEM_BYTES>>>(x, W_in, b_in, nullptr, gh, HID, 0,
                                                     nullptr, nullptr, nullptr);
    gemm_k<<<dim3(NN/64, 6), 256, GEMM_SMEM_BYTES>>>(gh, ipw, ipb, nullptr, nullptr, 3*HID, 2,
                                                     gqb, gkb, gvt);
    attn_k<<<NN/64, 256, ATTN_SMEM>>>(gqb, gkb, gvt, sp, scale, gao);
    gemm_k<<<dim3(NN/64, 2), 256, GEMM_SMEM_BYTES>>>(gao, opw, opb, gh, gh2, HID, 1,
                                                     nullptr, nullptr, nullptr);
    gemm_k<<<dim3(NN/64, 1), 256, GEMM_SMEM_BYTES>>>(gh2, Wout, bout, nullptr, out, OUTD, 0,
                                                     nullptr, nullptr, nullptr);
    logsoftmax_k<<<NN/8, 256>>>(out);
}

// round 11
// speedup vs baseline: 4.0739x; 3.6837x over previous
#include <cuda_runtime.h>
#include <cuda_fp16.h>
#include <math_constants.h>
#include <cstdint>

#define NN    8192
#define HID   128
#define OUTD  40
#define RSQRT_HD 0.17677669529663687f
#define L2E      1.4426950408889634f
#define MSH      (-4.0f * 1.4426950408889634f)   // -(4)*log2e fixed shift

__device__ float  g_h  [NN * HID];
__device__ __half g_qh [NN * HID];
__device__ __half g_kh [NN * HID];
__device__ __half g_vt [HID * NN];
__device__ float  g_ao [NN * HID];
__device__ float  g_h2 [NN * HID];

__device__ __forceinline__ uint32_t smem_u32(const void* p){
    uint32_t a;
    asm("{ .reg .u64 t; cvta.to.shared.u64 t, %1; cvt.u32.u64 %0, t; }" : "=r"(a) : "l"(p));
    return a;
}
__device__ __forceinline__ void ldsm4(uint32_t r[4], uint32_t addr){
    asm volatile("ldmatrix.sync.aligned.m8n8.x4.shared.b16 {%0,%1,%2,%3}, [%4];"
        : "=r"(r[0]), "=r"(r[1]), "=r"(r[2]), "=r"(r[3]) : "r"(addr));
}
__device__ __forceinline__ void mmaf16(float c[4], const uint32_t a[4], const uint32_t b[2]){
    asm volatile("mma.sync.aligned.m16n8k16.row.col.f32.f16.f16.f32 "
        "{%0,%1,%2,%3}, {%4,%5,%6,%7}, {%8,%9}, {%0,%1,%2,%3};"
        : "+f"(c[0]), "+f"(c[1]), "+f"(c[2]), "+f"(c[3])
        : "r"(a[0]), "r"(a[1]), "r"(a[2]), "r"(a[3]), "r"(b[0]), "r"(b[1]));
}
__device__ __forceinline__ uint32_t packh2(float hi, float lo){
    uint32_t r; asm("cvt.rn.f16x2.f32 %0, %1, %2;" : "=r"(r) : "f"(hi), "f"(lo)); return r;
}
__device__ __forceinline__ uint32_t ex2h2(uint32_t a){
    uint32_t d; asm("ex2.approx.f16x2 %0, %1;" : "=r"(d) : "r"(a)); return d;
}
__device__ __forceinline__ uint32_t mulh2(uint32_t a, uint32_t b){
    uint32_t d; asm("mul.rn.f16x2 %0, %1, %2;" : "=r"(d) : "r"(a), "r"(b)); return d;
}
__device__ __forceinline__ uint32_t addh2(uint32_t a, uint32_t b){
    uint32_t d; asm("add.rn.f16x2 %0, %1, %2;" : "=r"(d) : "r"(a), "r"(b)); return d;
}
__device__ __forceinline__ float2 h2f2(uint32_t h){
    __half2 v = *(__half2*)&h; return __half22float2(v);
}
// E' = exp(bias - scale) as f16 bits; LUT fast path for integer sp in [0,10]
__device__ __forceinline__ uint32_t e16(float s, uint32_t lutaddr, float scale){
    int idx = __float2int_rn(s);
    uint32_t h;
    if (__int2float_rn(idx) == s && idx >= 0 && idx <= 10) {
        asm volatile("ld.shared.u16 %0, [%1];" : "=r"(h) : "r"(lutaddr + idx*2));
    } else {
        float ss = (isnan(s) || isinf(s)) ? -1.0f : s;
        float r = __fdividef(1.0f, ss);
        if (isnan(r) || isinf(r)) r = 0.0f;
        float e = exp2f(fmaf(scale, r, -scale) * L2E);
        h = (uint32_t)__half_as_ushort(__float2half_rn(e));
    }
    return h;
}

// ---------------- GEMM (R6 structure; mode2 emits f16 Q/K/V^T) ----------------
#define GEMM_SMEM_BYTES ((2*128*64 + 64*132) * 4)

__global__ __launch_bounds__(256, 2)
void gemm_k(const float* __restrict__ A, const float* __restrict__ W,
            const float* __restrict__ bias, const float* __restrict__ R,
            float* __restrict__ C, int CO, int mode,
            __half* __restrict__ qh, __half* __restrict__ kh, __half* __restrict__ vt)
{
    extern __shared__ float sm[];
    float* At  = sm;
    float* Wt  = sm + 128*64;
    float* Stg = sm + 2*128*64;
    const int r0  = blockIdx.x * 64;
    const int c0  = blockIdx.y * 64;
    const int tid = threadIdx.x;

    {
        const float4* Af4 = (const float4*)(A + (size_t)r0 * 128);
        float4* Sf4 = (float4*)Stg;
        #pragma unroll
        for (int i = 0; i < 8; i++) {
            int idx = tid + 256*i;
            int r = idx >> 5, d4 = idx & 31;
            Sf4[r*33 + d4] = Af4[r*32 + d4];
        }
    }
    __syncthreads();
    {
        #pragma unroll
        for (int i = 0; i < 8; i++) {
            int idx = tid + 256*i;
            int r = idx & 63, d4 = idx >> 6;
            float4 v = *(const float4*)&Stg[r*132 + d4*4];
            At[(4*d4+0)*64 + r] = v.x; At[(4*d4+1)*64 + r] = v.y;
            At[(4*d4+2)*64 + r] = v.z; At[(4*d4+3)*64 + r] = v.w;
        }
    }
    __syncthreads();
    {
        const float4* Wf4 = (const float4*)W;
        float4* Sf4 = (float4*)Stg;
        #pragma unroll
        for (int i = 0; i < 8; i++) {
            int idx = tid + 256*i;
            int c = idx >> 5, d4 = idx & 31;
            float4 v = make_float4(0.f,0.f,0.f,0.f);
            if (c0 + c < CO) v = Wf4[(size_t)(c0 + c)*32 + d4];
            Sf4[c*33 + d4] = v;
        }
    }
    __syncthreads();
    {
        #pragma unroll
        for (int i = 0; i < 8; i++) {
            int idx = tid + 256*i;
            int c = idx & 63, d4 = idx >> 6;
            float4 v = *(const float4*)&Stg[c*132 + d4*4];
            Wt[(4*d4+0)*64 + c] = v.x; Wt[(4*d4+1)*64 + c] = v.y;
            Wt[(4*d4+2)*64 + c] = v.z; Wt[(4*d4+3)*64 + c] = v.w;
        }
    }
    __syncthreads();

    const int tr = tid >> 4;
    const int tc = tid & 15;
    float acc[4][4];
    #pragma unroll
    for (int i = 0; i < 4; i++)
        #pragma unroll
        for (int j = 0; j < 4; j++) acc[i][j] = 0.f;

    #pragma unroll 8
    for (int d = 0; d < 128; d++) {
        float4 a = *(const float4*)&At[d*64 + tr*4];
        float4 w = *(const float4*)&Wt[d*64 + tc*4];
        float av[4] = {a.x, a.y, a.z, a.w};
        float wv[4] = {w.x, w.y, w.z, w.w};
        #pragma unroll
        for (int i = 0; i < 4; i++)
            #pragma unroll
            for (int j = 0; j < 4; j++)
                acc[i][j] = fmaf(av[i], wv[j], acc[i][j]);
    }

    #pragma unroll
    for (int i = 0; i < 4; i++) {
        int r = r0 + tr*4 + i;
        #pragma unroll
        for (int j = 0; j < 4; j++) {
            int c = c0 + tc*4 + j;
            if (c < CO) {
                float v = acc[i][j] + bias[c];
                if (mode == 2) {
                    if (c < 128)      qh[(size_t)r*128 + c]       = __float2half_rn(v * RSQRT_HD);
                    else if (c < 256) kh[(size_t)r*128 + (c-128)] = __float2half_rn(v);
                    else              vt[(size_t)(c-256)*NN + r]  = __float2half_rn(v);
                } else {
                    if (mode == 1) v = R[(size_t)r*128 + c] + fmaxf(v, 0.f);
                    C[(size_t)r*CO + c] = v;
                }
            }
        }
    }
}

// ---------------- flash attention: 64q x 4 heads, double-buffered, 1 sync/iter ---
// Stage: Ks [64k][272B] @0, Vs [128d][144B] @17408, Es f16 [64q][144B] @35840 (9216B)
// Es row layout (permuted): pair (2k,2k+1) f16x2 at byte c*32 + j*4, c=k2&3? see code.
#define STAGE     45056
#define LUT_OFF   90112
#define ATTN_SMEM 90240

__global__ __launch_bounds__(256, 1)
void attn_k(const __half* __restrict__ qh_g, const __half* __restrict__ kh_g,
            const __half* __restrict__ vt_g, const float* __restrict__ sp,
            const float* __restrict__ scale_ptr, float* __restrict__ out)
{
    extern __shared__ char smc[];
    const uint32_t sb = smem_u32(smc);
    const int tid  = threadIdx.x;
    const int lane = tid & 31;
    const int wid  = tid >> 5;
    const int h    = wid >> 1;
    const int qhf  = wid & 1;
    const int q0   = blockIdx.x * 64;
    const float scale = scale_ptr[0];
    const uint32_t lut = sb + LUT_OFF;

    // ---- LUT (11 entries) + stage Q into stage1 Ks region ----
    if (tid <= 10) {
        float e = (tid == 0) ? expf(-scale) : expf(scale / (float)tid - scale);
        uint32_t hb = (uint32_t)__half_as_ushort(__float2half_rn(e));
        asm volatile("st.shared.u16 [%0], %1;" :: "r"(lut + tid*2), "r"(hb));
    }
    {
        const uint4* qsrc = (const uint4*)(qh_g + (size_t)q0 * 128);
        #pragma unroll
        for (int i = 0; i < 4; i++) {
            int idx = tid + 256*i;
            int r = idx >> 4, c = idx & 15;
            *(uint4*)(smc + STAGE + r*272 + c*16) = qsrc[r*16 + c];
        }
    }
    __syncthreads();
    uint32_t qa[2][2][4];
    #pragma unroll
    for (int mt = 0; mt < 2; mt++) {
        uint32_t qaddr = sb + STAGE + (qhf*32 + mt*16 + (lane & 15))*272
                         + (h*4 + (lane >> 4))*16;
        ldsm4(qa[mt][0], qaddr);
        ldsm4(qa[mt][1], qaddr + 32);
    }

    const uint32_t kaddr0 = sb + ((lane & 7) + ((lane >> 4) & 1)*8)*272
                            + h*64 + ((lane >> 3) & 1)*16;
    const uint32_t vaddr0 = sb + 17408 + (h*32 + (lane & 7) + ((lane >> 4) & 1)*8)*144
                            + ((lane >> 3) & 1)*16;
    const uint32_t baddr0 = sb + 35840 + (qhf*32 + (lane >> 2))*144 + (lane & 3)*32;

    float O[2][4][4];
    #pragma unroll
    for (int mt = 0; mt < 2; mt++)
        #pragma unroll
        for (int i = 0; i < 4; i++)
            #pragma unroll
            for (int j = 0; j < 4; j++) O[mt][i][j] = 0.f;
    float lsum[2][2] = {{0.f,0.f},{0.f,0.f}};

    const uint4* ksrc = (const uint4*)kh_g;   // token row = 16 uint4
    const uint4* vsrc = (const uint4*)vt_g;   // d row = 1024 uint4

    const int kr = tid >> 4, kc = tid & 15;
    const int vr = tid >> 3, vc = tid & 7;
    // bias STS permuted addresses (pair indices 2kc, 2kc+1)
    const int bj  = kc >> 1;
    const int bc0 = (2*kc) & 3, bc1 = (2*kc + 1) & 3;

    uint4  krg[4], vrg[4];
    float4 brg[4];
    #pragma unroll
    for (int i = 0; i < 4; i++) {           // tile 0
        krg[i] = ksrc[(size_t)(kr + 16*i)*16 + kc];
        vrg[i] = vsrc[(size_t)(vr + 32*i)*1024 + vc];
        brg[i] = *(const float4*)(sp + (size_t)(q0 + kr + 16*i)*NN + kc*4);
    }
    {   // write stage0, then preload tile1
        #pragma unroll
        for (int i = 0; i < 4; i++) {
            *(uint4*)(smc + (kr + 16*i)*272 + kc*16) = krg[i];
            *(uint4*)(smc + 17408 + (vr + 32*i)*144 + vc*16) = vrg[i];
            float4 s4 = brg[i];
            uint32_t p0 = (e16(s4.y, lut, scale) << 16) | e16(s4.x, lut, scale);
            uint32_t p1 = (e16(s4.w, lut, scale) << 16) | e16(s4.z, lut, scale);
            uint32_t bb = 35840 + (kr + 16*i)*144 + bj*4;
            *(uint32_t*)(smc + bb + bc0*32) = p0;
            *(uint32_t*)(smc + bb + bc1*32) = p1;
        }
        #pragma unroll
        for (int i = 0; i < 4; i++) {
            krg[i] = ksrc[(size_t)(64 + kr + 16*i)*16 + kc];
            vrg[i] = vsrc[(size_t)(vr + 32*i)*1024 + 8 + vc];
            brg[i] = *(const float4*)(sp + (size_t)(q0 + kr + 16*i)*NN + 64 + kc*4);
        }
    }

    for (int kb = 0; kb < NN/64; kb++) {
        __syncthreads();
        const uint32_t cur = (kb & 1) * STAGE;
        const uint32_t nxt = ((kb + 1) & 1) * STAGE;

        if (kb < NN/64 - 1) {   // write next stage from prefetched regs
            #pragma unroll
            for (int i = 0; i < 4; i++) {
                *(uint4*)(smc + nxt + (kr + 16*i)*272 + kc*16) = krg[i];
                *(uint4*)(smc + nxt + 17408 + (vr + 32*i)*144 + vc*16) = vrg[i];
                float4 s4 = brg[i];
                uint32_t p0 = (e16(s4.y, lut, scale) << 16) | e16(s4.x, lut, scale);
                uint32_t p1 = (e16(s4.w, lut, scale) << 16) | e16(s4.z, lut, scale);
                uint32_t bb = nxt + 35840 + (kr + 16*i)*144 + bj*4;
                *(uint32_t*)(smc + bb + bc0*32) = p0;
                *(uint32_t*)(smc + bb + bc1*32) = p1;
            }
        }
        if (kb < NN/64 - 2) {   // prefetch tile kb+2
            const int k0n = (kb + 2) * 64;
            #pragma unroll
            for (int i = 0; i < 4; i++) {
                krg[i] = ksrc[(size_t)(k0n + kr + 16*i)*16 + kc];
                vrg[i] = vsrc[(size_t)(vr + 32*i)*1024 + (k0n >> 3) + vc];
                brg[i] = *(const float4*)(sp + (size_t)(q0 + kr + 16*i)*NN + k0n + kc*4);
            }
        }

        // ---- S = Q K^T ----
        float S[2][8][4];
        #pragma unroll
        for (int mt = 0; mt < 2; mt++)
            #pragma unroll
            for (int j = 0; j < 8; j++)
                #pragma unroll
                for (int t = 0; t < 4; t++) S[mt][j][t] = 0.f;
        #pragma unroll
        for (int s = 0; s < 2; s++) {
            #pragma unroll
            for (int p = 0; p < 4; p++) {
                uint32_t kbf[4];
                ldsm4(kbf, kaddr0 + cur + p*(16*272) + s*32);
                #pragma unroll
                for (int mt = 0; mt < 2; mt++) {
                    mmaf16(S[mt][2*p],   qa[mt][s], kbf);
                    mmaf16(S[mt][2*p+1], qa[mt][s], kbf + 2);
                }
            }
        }

        // ---- softmax: p = ex2((S-4)*L2E) * E', all f16x2 ----
        uint32_t pk[2][4][4];
        #pragma unroll
        for (int mt = 0; mt < 2; mt++) {
            const uint32_t bmt = baddr0 + cur + mt*(16*144);
            uint32_t eL[4], eL2[4], eH[4], eH2[4];
            *(uint4*)eL  = *(const uint4*)(size_t)0; // placeholder avoided below
            asm volatile("ld.shared.v4.b32 {%0,%1,%2,%3}, [%4];"
                : "=r"(eL[0]),"=r"(eL[1]),"=r"(eL[2]),"=r"(eL[3]) : "r"(bmt));
            asm volatile("ld.shared.v4.b32 {%0,%1,%2,%3}, [%4];"
                : "=r"(eL2[0]),"=r"(eL2[1]),"=r"(eL2[2]),"=r"(eL2[3]) : "r"(bmt + 16));
            asm volatile("ld.shared.v4.b32 {%0,%1,%2,%3}, [%4];"
                : "=r"(eH[0]),"=r"(eH[1]),"=r"(eH[2]),"=r"(eH[3]) : "r"(bmt + 8*144));
            asm volatile("ld.shared.v4.b32 {%0,%1,%2,%3}, [%4];"
                : "=r"(eH2[0]),"=r"(eH2[1]),"=r"(eH2[2]),"=r"(eH2[3]) : "r"(bmt + 8*144 + 16));
            uint32_t laccL = 0, laccH = 0;
            #pragma unroll
            for (int j = 0; j < 8; j++) {
                uint32_t ePL = (j < 4) ? eL[j] : eL2[j-4];
                uint32_t ePH = (j < 4) ? eH[j] : eH2[j-4];
                uint32_t u0 = ex2h2(packh2(fmaf(S[mt][j][1], L2E, MSH),
                                           fmaf(S[mt][j][0], L2E, MSH)));
                uint32_t u1 = ex2h2(packh2(fmaf(S[mt][j][3], L2E, MSH),
                                           fmaf(S[mt][j][2], L2E, MSH)));
                uint32_t pk0 = mulh2(u0, ePL);
                uint32_t pk1 = mulh2(u1, ePH);
                laccL = addh2(laccL, pk0);
                laccH = addh2(laccH, pk1);
                int s = j >> 1, o = (j & 1) * 2;
                pk[mt][s][o]     = pk0;
                pk[mt][s][o + 1] = pk1;
            }
            float2 fL = h2f2(laccL), fH = h2f2(laccH);
            lsum[mt][0] += fL.x + fL.y;
            lsum[mt][1] += fH.x + fH.y;
        }

        // ---- O += P V ----
        #pragma unroll
        for (int s = 0; s < 4; s++) {
            uint32_t vb[8];
            ldsm4(vb,     vaddr0 + cur + s*32);
            ldsm4(vb + 4, vaddr0 + cur + 16*144 + s*32);
            #pragma unroll
            for (int mt = 0; mt < 2; mt++) {
                mmaf16(O[mt][0], pk[mt][s], vb);
                mmaf16(O[mt][1], pk[mt][s], vb + 2);
                mmaf16(O[mt][2], pk[mt][s], vb + 4);
                mmaf16(O[mt][3], pk[mt][s], vb + 6);
            }
        }
    }

    // ---- finalize ----
    #pragma unroll
    for (int mt = 0; mt < 2; mt++) {
        float l0 = lsum[mt][0], l1 = lsum[mt][1];
        l0 += __shfl_xor_sync(0xffffffffu, l0, 1);
        l0 += __shfl_xor_sync(0xffffffffu, l0, 2);
        l1 += __shfl_xor_sync(0xffffffffu, l1, 1);
        l1 += __shfl_xor_sync(0xffffffffu, l1, 2);
        const float i0 = 1.0f / l0;
        const float i1 = 1.0f / l1;
        const int r  = q0 + qhf*32 + mt*16 + (lane >> 2);
        const int cb = h*32 + 2*(lane & 3);
        #pragma unroll
        for (int j = 0; j < 4; j++) {
            float2 v0 = make_float2(O[mt][j][0]*i0, O[mt][j][1]*i0);
            float2 v1 = make_float2(O[mt][j][2]*i1, O[mt][j][3]*i1);
            *(float2*)(out + (size_t)r*128 + cb + 8*j)     = v0;
            *(float2*)(out + (size_t)(r+8)*128 + cb + 8*j) = v1;
        }
    }
}

// ---------------- log_softmax ----------------
__global__ __launch_bounds__(256)
void logsoftmax_k(float* __restrict__ io)
{
    int row  = blockIdx.x * 8 + (threadIdx.x >> 5);
    int lane = threadIdx.x & 31;
    float* p = io + (size_t)row * OUTD;

    float a = p[lane];
    float b = (lane < 8) ? p[lane + 32] : -CUDART_INF_F;

    float mx = fmaxf(a, b);
    #pragma unroll
    for (int off = 16; off; off >>= 1)
        mx = fmaxf(mx, __shfl_xor_sync(0xffffffffu, mx, off));

    float e = __expf(a - mx) + ((lane < 8) ? __expf(b - mx) : 0.f);
    #pragma unroll
    for (int off = 16; off; off >>= 1)
        e += __shfl_xor_sync(0xffffffffu, e, off);

    float lse = mx + logf(e);
    p[lane] = a - lse;
    if (lane < 8) p[lane + 32] = b - lse;
}

// ---------------- launch ----------------
extern "C" void kernel_launch(void* const* d_in, const int* in_sizes, int n_in,
                              void* d_out, int out_size)
{
    (void)in_sizes; (void)n_in; (void)out_size;
    const float* x     = (const float*)d_in[0];
    const float* sp    = (const float*)d_in[2];
    const float* W_in  = (const float*)d_in[3];
    const float* b_in  = (const float*)d_in[4];
    const float* ipw   = (const float*)d_in[5];
    const float* ipb   = (const float*)d_in[6];
    const float* opw   = (const float*)d_in[7];
    const float* opb   = (const float*)d_in[8];
    const float* Wout  = (const float*)d_in[9];
    const float* bout  = (const float*)d_in[10];
    const float* scale = (const float*)d_in[11];
    float* out = (float*)d_out;

    float *gh, *gao, *gh2;
    __half *gq, *gk, *gv;
    cudaGetSymbolAddress((void**)&gh,  g_h);
    cudaGetSymbolAddress((void**)&gao, g_ao);
    cudaGetSymbolAddress((void**)&gh2, g_h2);
    cudaGetSymbolAddress((void**)&gq,  g_qh);
    cudaGetSymbolAddress((void**)&gk,  g_kh);
    cudaGetSymbolAddress((void**)&gv,  g_vt);

    cudaFuncSetAttribute(gemm_k, cudaFuncAttributeMaxDynamicSharedMemorySize, GEMM_SMEM_BYTES);
    cudaFuncSetAttribute(attn_k, cudaFuncAttributeMaxDynamicSharedMemorySize, ATTN_SMEM);

    gemm_k<<<dim3(NN/64, 2), 256, GEMM_SMEM_BYTES>>>(x, W_in, b_in, nullptr, gh, HID, 0,
                                                     nullptr, nullptr, nullptr);
    gemm_k<<<dim3(NN/64, 6), 256, GEMM_SMEM_BYTES>>>(gh, ipw, ipb, nullptr, nullptr, 3*HID, 2,
                                                     gq, gk, gv);
    attn_k<<<NN/64, 256, ATTN_SMEM>>>(gq, gk, gv, sp, scale, gao);
    gemm_k<<<dim3(NN/64, 2), 256, GEMM_SMEM_BYTES>>>(gao, opw, opb, gh, gh2, HID, 1,
                                                     nullptr, nullptr, nullptr);
    gemm_k<<<dim3(NN/64, 1), 256, GEMM_SMEM_BYTES>>>(gh2, Wout, bout, nullptr, out, OUTD, 0,
                                                     nullptr, nullptr, nullptr);
    logsoftmax_k<<<NN/8, 256>>>(out);
}